// round 11
// baseline (speedup 1.0000x reference)
#include <cuda_runtime.h>
#include <cuda_bf16.h>
#include <cstdint>

#define NS 500000
#define EPS 1e-5f

// interleaved split-bf16 h: per site 64 u32 (32 hi-pairs then 32 lo-pairs)
__device__ __align__(16) unsigned g_h[NS * 64];
// ldmatrix images for W1 (k-major [K][N+8]) and W3 ([64][136])
__device__ __align__(16) unsigned short gW1hi[128 * 72], gW1lo[128 * 72];
__device__ __align__(16) unsigned short gW3hi[64 * 136], gW3lo[64 * 136];
// transposed W2 for direct-LDG B fragments: [9][64 n][64 k]
__device__ __align__(16) unsigned short gW2thi[9 * 64 * 64], gW2tlo[9 * 64 * 64];

__device__ __forceinline__ uint32_t s2u(const void* p) {
    uint32_t a;
    asm("{ .reg .u64 t; cvta.to.shared.u64 t, %1; cvt.u32.u64 %0, t; }" : "=r"(a) : "l"(p));
    return a;
}
__device__ __forceinline__ float silu(float x) { return x / (1.0f + __expf(-x)); }
// truncation split: hi = top 16 bits (exact), lo = rn(x - hi). 2 elements at once.
__device__ __forceinline__ void split2(float x0, float x1, unsigned& hi, unsigned& lo) {
    unsigned u0 = __float_as_uint(x0), u1 = __float_as_uint(x1);
    asm("prmt.b32 %0, %1, %2, 0x7632;" : "=r"(hi) : "r"(u0), "r"(u1));
    float l0 = x0 - __uint_as_float(u0 & 0xffff0000u);
    float l1 = x1 - __uint_as_float(u1 & 0xffff0000u);
    asm("cvt.rn.bf16x2.f32 %0, %1, %2;" : "=r"(lo) : "f"(l1), "f"(l0));
}
__device__ __forceinline__ void cpa16(uint32_t dst, const void* src) {
    asm volatile("cp.async.ca.shared.global [%0], [%1], 16;" :: "r"(dst), "l"(src));
}
#define CP_COMMIT() asm volatile("cp.async.commit_group;" ::: "memory")
#define CP_WAIT0()  asm volatile("cp.async.wait_group 0;" ::: "memory")
#define CP_WAIT1()  asm volatile("cp.async.wait_group 1;" ::: "memory")
__device__ __forceinline__ void ldmA(unsigned r[4], uint32_t a) {
    asm volatile("ldmatrix.sync.aligned.m8n8.x4.shared.b16 {%0,%1,%2,%3}, [%4];"
                 : "=r"(r[0]), "=r"(r[1]), "=r"(r[2]), "=r"(r[3]) : "r"(a));
}
__device__ __forceinline__ void ldmB(unsigned r[2], uint32_t a) {
    asm volatile("ldmatrix.sync.aligned.m8n8.x2.trans.shared.b16 {%0,%1}, [%2];"
                 : "=r"(r[0]), "=r"(r[1]) : "r"(a));
}
__device__ __forceinline__ void mmab(float d[4], const unsigned a[4], const unsigned b[2]) {
    asm volatile(
        "mma.sync.aligned.m16n8k16.row.col.f32.bf16.bf16.f32 "
        "{%0,%1,%2,%3},{%4,%5,%6,%7},{%8,%9},{%0,%1,%2,%3};"
        : "+f"(d[0]), "+f"(d[1]), "+f"(d[2]), "+f"(d[3])
        : "r"(a[0]), "r"(a[1]), "r"(a[2]), "r"(a[3]), "r"(b[0]), "r"(b[1]));
}

__global__ void kdum() {}

// ============================================================================
// k0: build weight images (W1/W3 ldmatrix images, W2 transposed for LDG frags)
// ============================================================================
__global__ void k0(const float* __restrict__ W1, const float* __restrict__ W2,
                   const float* __restrict__ W3) {
    int i = blockIdx.x * 256 + threadIdx.x;
    float x;
    unsigned short *dh, *dl;
    int idx;
    if (i < 9216) {                       // W1: [128k][64n] -> [128][72]
        int k = i / 72, n = i % 72;
        x = (n < 64) ? W1[k * 64 + n] : 0.f;
        idx = i; dh = gW1hi; dl = gW1lo;
    } else if (i < 46080) {               // W2t: [9][64 n][64 k] = W2[kk][k][n]
        int j = i - 9216;
        int kk = j >> 12, r = j & 4095, n = r >> 6, k = r & 63;
        x = W2[kk * 4096 + k * 64 + n];
        idx = j; dh = gW2thi; dl = gW2tlo;
    } else if (i < 54784) {               // W3: [64k][128n] -> [64][136]
        int j = i - 46080;
        int ki = j / 136, n = j % 136;
        x = (n < 128) ? W3[ki * 128 + n] : 0.f;
        idx = j; dh = gW3hi; dl = gW3lo;
    } else return;
    __nv_bfloat16 h = __float2bfloat16(x);
    dh[idx] = __bfloat16_as_ushort(h);
    dl[idx] = __bfloat16_as_ushort(__float2bfloat16(x - __bfloat162float(h)));
}

// ============================================================================
// k1: h = silu(bn1(feat @ W1))  [128 rows/block, 256 thr, warp = 16 rows]
// ============================================================================
#define O_B1HI 0
#define O_B1LO 18432
#define O_A1HI 36864
#define O_A1LO 47104
#define O_P1SC 57344
#define O_P1TB 57600
#define SM1    57856

__global__ __launch_bounds__(256, 3) void k1(
    const float* __restrict__ feat,
    const float* __restrict__ g1, const float* __restrict__ b1,
    const float* __restrict__ m1, const float* __restrict__ v1)
{
    extern __shared__ char sm[];
    uint32_t sb = s2u(sm);
    int t = threadIdx.x, wid = t >> 5, lane = t & 31;
    int base = blockIdx.x * 128;

    for (int q = t; q < 2304; q += 256) {
        if (q < 1152) cpa16(sb + O_B1HI + q * 16, gW1hi + q * 8);
        else          cpa16(sb + O_B1LO + (q - 1152) * 16, gW1lo + (q - 1152) * 8);
    }
    CP_COMMIT();
    if (t < 64) {
        float s = g1[t] * rsqrtf(v1[t] + EPS);
        ((float*)(sm + O_P1SC))[t] = s;
        ((float*)(sm + O_P1TB))[t] = b1[t] - m1[t] * s;
    }

    float d[8][4] = {};
    int arow = ((lane >> 3) & 1) * 8 + (lane & 7);
    int acol = (lane >> 4) * 16;
    int brow = arow;

    for (int kc = 0; kc < 4; kc++) {
        __syncthreads();
        #pragma unroll
        for (int i = 0; i < 4; i++) {
            int idx = t + 256 * i, r = idx >> 3, p = idx & 7;
            int site = base + r;
            float4 f = (site < NS) ? ((const float4*)feat)[(size_t)site * 32 + kc * 8 + p]
                                   : make_float4(0.f, 0.f, 0.f, 0.f);
            unsigned h0, l0, h1, l1;
            split2(f.x, f.y, h0, l0);
            split2(f.z, f.w, h1, l1);
            *(uint2*)(sm + O_A1HI + r * 80 + p * 8) = make_uint2(h0, h1);
            *(uint2*)(sm + O_A1LO + r * 80 + p * 8) = make_uint2(l0, l1);
        }
        CP_WAIT0();
        __syncthreads();
        unsigned ah[2][4], al[2][4];
        #pragma unroll
        for (int kq = 0; kq < 2; kq++) {
            uint32_t a = sb + O_A1HI + (wid * 16 + arow) * 80 + kq * 32 + acol;
            ldmA(ah[kq], a);
            ldmA(al[kq], a + (O_A1LO - O_A1HI));
        }
        #pragma unroll
        for (int n8 = 0; n8 < 8; n8++) {
            unsigned bh[2][2], bl[2][2];
            #pragma unroll
            for (int kq = 0; kq < 2; kq++) {
                uint32_t a = sb + O_B1HI + (kc * 32 + kq * 16 + brow) * 144 + n8 * 16;
                ldmB(bh[kq], a);
                ldmB(bl[kq], a + (O_B1LO - O_B1HI));
            }
            #pragma unroll
            for (int kq = 0; kq < 2; kq++) {
                mmab(d[n8], ah[kq], bh[kq]);
                mmab(d[n8], ah[kq], bl[kq]);
                mmab(d[n8], al[kq], bh[kq]);
            }
        }
    }
    const float* sc = (const float*)(sm + O_P1SC);
    const float* tb = (const float*)(sm + O_P1TB);
    #pragma unroll
    for (int n8 = 0; n8 < 8; n8++) {
        int c = 8 * n8 + 2 * (lane & 3);
        float s0 = sc[c], s1 = sc[c + 1], t0 = tb[c], t1 = tb[c + 1];
        #pragma unroll
        for (int h = 0; h < 2; h++) {
            int site = base + wid * 16 + (lane >> 2) + 8 * h;
            if (site < NS) {
                float o0 = silu(d[n8][2 * h] * s0 + t0);
                float o1 = silu(d[n8][2 * h + 1] * s1 + t1);
                unsigned hw, lw;
                split2(o0, o1, hw, lw);
                g_h[(size_t)site * 64 + (c >> 1)] = hw;
                g_h[(size_t)site * 64 + 32 + (c >> 1)] = lw;
            }
        }
    }
}

// ============================================================================
// k2: cv2 via flat 16-row tile list, 8 tiles (128 rows) per double-buffered
//     item (2 barriers per ~8 tiles), W2 B-frags via LDG from L2-hot W2t;
//     then BN2/SiLU + cv3 + BN3 + residual + SiLU.
// ============================================================================
#define O_ACC  0           // f32 [128][66] = 33792
#define O_LP   33792       // u32 [9][128] packed (id<<8 | row)
#define O_CN   38400       // int[12]
#define O_TL   38448       // int[80] tile descs (k*128 + c0)
#define O_NT   38768       // int
#define O_SC2  38784
#define O_TB2  39040
#define O_SC3  39296
#define O_TB3  39808
#define O_G0   40320       // item slot 0: hi[128*144] + lo[128*144] = 36864
#define O_G1   77184       // item slot 1
#define SM2    114048
#define O_W3HI 0           // post-cv2: W3 image over ACC/LP region
#define O_W3LO 17408
#define O_A3HI 40320       // A3 tile over slot 0
#define O_A3LO 58752

__global__ __launch_bounds__(256) void k2(
    const float* __restrict__ feat, const int* __restrict__ nbr,
    const float* __restrict__ g2, const float* __restrict__ b2,
    const float* __restrict__ m2, const float* __restrict__ v2,
    const float* __restrict__ g3, const float* __restrict__ b3,
    const float* __restrict__ m3, const float* __restrict__ v3,
    float* __restrict__ out)
{
    extern __shared__ char sm[];
    uint32_t sb = s2u(sm);
    int t = threadIdx.x, wid = t >> 5, lane = t & 31;
    int base = blockIdx.x * 128;
    unsigned* lp = (unsigned*)(sm + O_LP);
    int* cnt9 = (int*)(sm + O_CN);
    int* tl = (int*)(sm + O_TL);
    float* acc = (float*)(sm + O_ACC);

    if (t < 64) {
        float s = g2[t] * rsqrtf(v2[t] + EPS);
        ((float*)(sm + O_SC2))[t] = s;
        ((float*)(sm + O_TB2))[t] = b2[t] - m2[t] * s;
    }
    if (t < 128) {
        float s = g3[t] * rsqrtf(v3[t] + EPS);
        ((float*)(sm + O_SC3))[t] = s;
        ((float*)(sm + O_TB3))[t] = b3[t] - m3[t] * s;
    }
    #pragma unroll
    for (int i = 0; i < 33; i++) acc[t + 256 * i] = 0.f;

    // compaction: warp w handles offsets w, w+8
    for (int k = wid; k < 9; k += 8) {
        int cbase = 0;
        #pragma unroll
        for (int g = 0; g < 4; g++) {
            int site = base + g * 32 + lane;
            int id = (site < NS) ? __ldg(&nbr[(size_t)k * NS + site]) : NS;
            bool val = id < NS;
            unsigned msk = __ballot_sync(0xffffffffu, val);
            if (val) {
                int p = cbase + __popc(msk & ((1u << lane) - 1u));
                lp[k * 128 + p] = ((unsigned)id << 8) | (g * 32 + lane);
            }
            cbase += __popc(msk);
        }
        if (lane == 0) cnt9[k] = cbase;
    }
    __syncthreads();
    if (t == 0) {   // flat tile list: 16-row tiles per offset
        int nt = 0;
        for (int k = 0; k < 9; k++)
            for (int c0 = 0; c0 < cnt9[k]; c0 += 16)
                tl[nt++] = k * 128 + c0;
        *(int*)(sm + O_NT) = nt;
    }
    __syncthreads();
    int nt = *(int*)(sm + O_NT);
    int nitems = (nt + 7) >> 3;

    auto issue_item = [&](int j) {
        uint32_t slot = sb + ((j & 1) ? O_G1 : O_G0);
        for (int q = t; q < 2048; q += 256) {
            int tile = q >> 8, rr = (q >> 4) & 15, s = q & 15;
            int ti = j * 8 + tile;
            if (ti < nt) {
                int d = tl[ti];
                int kk = d >> 7, c0 = d & 127;
                int gr = c0 + rr;
                if (gr < cnt9[kk]) {
                    unsigned id = lp[kk * 128 + gr] >> 8;
                    uint32_t dst = (s < 8) ? slot + (tile * 16 + rr) * 144 + s * 16
                                           : slot + 18432 + (tile * 16 + rr) * 144 + (s - 8) * 16;
                    cpa16(dst, g_h + (size_t)id * 64 + s * 4);
                }
            }
        }
    };

    int arow = ((lane >> 3) & 1) * 8 + (lane & 7);
    int acol = (lane >> 4) * 16;
    int brow = arow;

    issue_item(0);
    CP_COMMIT();

    for (int it = 0; it < nitems; it++) {
        __syncthreads();
        if (it + 1 < nitems) issue_item(it + 1);
        CP_COMMIT();
        if (it + 1 < nitems) CP_WAIT1(); else CP_WAIT0();
        __syncthreads();

        uint32_t slot = sb + ((it & 1) ? O_G1 : O_G0);
        int tmax = min(nt - it * 8, 8);
        for (int tile = 0; tile < tmax; tile++) {
            int d = tl[it * 8 + tile];
            int kk = d >> 7, c0 = d & 127;
            int m = cnt9[kk];
            // B fragments via LDG.32 from L2-hot W2t (n = 8*wid + lane>>2)
            const unsigned short* wth = gW2thi + kk * 4096 + (8 * wid + (lane >> 2)) * 64 + (lane & 3) * 2;
            const unsigned short* wtl = gW2tlo + kk * 4096 + (8 * wid + (lane >> 2)) * 64 + (lane & 3) * 2;
            unsigned bhf[4][2], blf[4][2];
            #pragma unroll
            for (int kq = 0; kq < 4; kq++) {
                bhf[kq][0] = *(const unsigned*)(wth + kq * 16);
                bhf[kq][1] = *(const unsigned*)(wth + kq * 16 + 8);
                blf[kq][0] = *(const unsigned*)(wtl + kq * 16);
                blf[kq][1] = *(const unsigned*)(wtl + kq * 16 + 8);
            }
            unsigned ah[4][4], al[4][4];
            #pragma unroll
            for (int kq = 0; kq < 4; kq++) {
                uint32_t a = slot + (tile * 16 + arow) * 144 + kq * 32 + acol;
                ldmA(ah[kq], a);
                ldmA(al[kq], a + 18432);
            }
            float dd[4] = {};
            #pragma unroll
            for (int kq = 0; kq < 4; kq++) {
                mmab(dd, ah[kq], bhf[kq]);
                mmab(dd, ah[kq], blf[kq]);
                mmab(dd, al[kq], bhf[kq]);
            }
            int c = 8 * wid + 2 * (lane & 3);
            #pragma unroll
            for (int h = 0; h < 2; h++) {
                int gr = c0 + (lane >> 2) + 8 * h;
                if (gr < m) {
                    int rw = lp[kk * 128 + gr] & 255;
                    float2* ap = (float2*)(acc + rw * 66 + c);
                    float2 v = *ap;
                    v.x += dd[2 * h]; v.y += dd[2 * h + 1];
                    *ap = v;
                }
            }
        }
    }
    __syncthreads();
    // BN2 + SiLU -> split bf16 A3 tile (over slot 0)
    const float* sc2 = (const float*)(sm + O_SC2);
    const float* tb2 = (const float*)(sm + O_TB2);
    #pragma unroll
    for (int i = 0; i < 16; i++) {
        int idx = t + 256 * i, r = idx >> 5, p = idx & 31;
        float x0 = acc[r * 66 + 2 * p] * sc2[2 * p] + tb2[2 * p];
        float x1 = acc[r * 66 + 2 * p + 1] * sc2[2 * p + 1] + tb2[2 * p + 1];
        x0 = silu(x0); x1 = silu(x1);
        unsigned hw, lw;
        split2(x0, x1, hw, lw);
        *(unsigned*)(sm + O_A3HI + r * 144 + p * 4) = hw;
        *(unsigned*)(sm + O_A3LO + r * 144 + p * 4) = lw;
    }
    __syncthreads();   // ACC reads done before W3 overwrites it
    for (int q = t; q < 2176; q += 256) {
        if (q < 1088) cpa16(sb + O_W3HI + q * 16, gW3hi + q * 8);
        else          cpa16(sb + O_W3LO + (q - 1088) * 16, gW3lo + (q - 1088) * 8);
    }
    CP_COMMIT();
    CP_WAIT0();
    __syncthreads();
    // cv3: warp = 16 rows x all 128 cols (per-n8 streaming epilogue)
    const float* sc3 = (const float*)(sm + O_SC3);
    const float* tb3 = (const float*)(sm + O_TB3);
    unsigned ah[4][4], al[4][4];
    #pragma unroll
    for (int kq = 0; kq < 4; kq++) {
        uint32_t a = sb + O_A3HI + (wid * 16 + arow) * 144 + kq * 32 + acol;
        ldmA(ah[kq], a);
        ldmA(al[kq], a + (O_A3LO - O_A3HI));
    }
    #pragma unroll
    for (int half = 0; half < 2; half++)
        #pragma unroll
        for (int n8 = 0; n8 < 8; n8++) {
            unsigned b_h[4][2], b_l[4][2];
            #pragma unroll
            for (int kq = 0; kq < 4; kq++) {
                uint32_t a = sb + O_W3HI + (kq * 16 + brow) * 272 + half * 128 + n8 * 16;
                ldmB(b_h[kq], a);
                ldmB(b_l[kq], a + (O_W3LO - O_W3HI));
            }
            float dd[4] = {};
            #pragma unroll
            for (int kq = 0; kq < 4; kq++) {
                mmab(dd, ah[kq], b_h[kq]);
                mmab(dd, ah[kq], b_l[kq]);
                mmab(dd, al[kq], b_h[kq]);
            }
            int c = 64 * half + 8 * n8 + 2 * (lane & 3);
            float s0 = sc3[c], s1 = sc3[c + 1], t0 = tb3[c], t1 = tb3[c + 1];
            #pragma unroll
            for (int h = 0; h < 2; h++) {
                int site = base + wid * 16 + (lane >> 2) + 8 * h;
                if (site < NS) {
                    float2 f = *(const float2*)(feat + (size_t)site * 128 + c);
                    float o0 = silu(dd[2 * h] * s0 + t0 + f.x);
                    float o1 = silu(dd[2 * h + 1] * s1 + t1 + f.y);
                    *(float2*)(out + (size_t)site * 128 + c) = make_float2(o0, o1);
                }
            }
        }
}

// ============================================================================
extern "C" void kernel_launch(void* const* d_in, const int* in_sizes, int n_in,
                              void* d_out, int out_size) {
    const float* feat = (const float*)d_in[0];
    const int*   nbr  = (const int*)d_in[1];
    const float* W1 = (const float*)d_in[2];
    const float* W2 = (const float*)d_in[3];
    const float* W3 = (const float*)d_in[4];
    const float* g1 = (const float*)d_in[5];
    const float* b1 = (const float*)d_in[6];
    const float* m1 = (const float*)d_in[7];
    const float* v1 = (const float*)d_in[8];
    const float* g2 = (const float*)d_in[9];
    const float* b2 = (const float*)d_in[10];
    const float* m2 = (const float*)d_in[11];
    const float* v2 = (const float*)d_in[12];
    const float* g3 = (const float*)d_in[13];
    const float* b3 = (const float*)d_in[14];
    const float* m3 = (const float*)d_in[15];
    const float* v3 = (const float*)d_in[16];
    float* out = (float*)d_out;

    cudaFuncSetAttribute(k1, cudaFuncAttributeMaxDynamicSharedMemorySize, SM1);
    cudaFuncSetAttribute(k2, cudaFuncAttributeMaxDynamicSharedMemorySize, SM2);

    int grid = (NS + 127) / 128;   // 3907
    kdum<<<1, 32>>>();
    k0<<<214, 256>>>(W1, W2, W3);
    k1<<<grid, 256, SM1>>>(feat, g1, b1, m1, v1);
    k2<<<grid, 256, SM2>>>(feat, nbr, g2, b2, m2, v2, g3, b3, m3, v3, out);
}

// round 14
// speedup vs baseline: 1.4006x; 1.4006x over previous
#include <cuda_runtime.h>
#include <cuda_bf16.h>
#include <cstdint>

#define NS 500000
#define EPS 1e-5f

// split-bf16 hidden activations: 2 channels packed per u32, 32 u32 per site
__device__ __align__(16) unsigned g_hhi[NS * 32];
__device__ __align__(16) unsigned g_hlo[NS * 32];
// padded ldmatrix-ready weight images: [K][N+pad] u16, built by k0
__device__ __align__(16) unsigned short gW1hi[128 * 72], gW1lo[128 * 72];
__device__ __align__(16) unsigned short gW2hi[9 * 64 * 72], gW2lo[9 * 64 * 72];
__device__ __align__(16) unsigned short gW3hi[64 * 136], gW3lo[64 * 136];

__device__ __forceinline__ uint32_t s2u(const void* p) {
    uint32_t a;
    asm("{ .reg .u64 t; cvta.to.shared.u64 t, %1; cvt.u32.u64 %0, t; }" : "=r"(a) : "l"(p));
    return a;
}
__device__ __forceinline__ float silu(float x) { return x / (1.0f + __expf(-x)); }
// truncation split: hi = top 16 bits (exact), lo = rn(x - hi). 2 elements at once.
__device__ __forceinline__ void split2(float x0, float x1, unsigned& hi, unsigned& lo) {
    unsigned u0 = __float_as_uint(x0), u1 = __float_as_uint(x1);
    asm("prmt.b32 %0, %1, %2, 0x7632;" : "=r"(hi) : "r"(u0), "r"(u1));
    float l0 = x0 - __uint_as_float(u0 & 0xffff0000u);
    float l1 = x1 - __uint_as_float(u1 & 0xffff0000u);
    asm("cvt.rn.bf16x2.f32 %0, %1, %2;" : "=r"(lo) : "f"(l1), "f"(l0));
}
__device__ __forceinline__ void cpa16(uint32_t dst, const void* src) {
    asm volatile("cp.async.ca.shared.global [%0], [%1], 16;" :: "r"(dst), "l"(src));
}
#define CP_COMMIT() asm volatile("cp.async.commit_group;" ::: "memory")
#define CP_WAIT0()  asm volatile("cp.async.wait_group 0;" ::: "memory")
#define CP_WAIT1()  asm volatile("cp.async.wait_group 1;" ::: "memory")
__device__ __forceinline__ void ldmA(unsigned r[4], uint32_t a) {
    asm volatile("ldmatrix.sync.aligned.m8n8.x4.shared.b16 {%0,%1,%2,%3}, [%4];"
                 : "=r"(r[0]), "=r"(r[1]), "=r"(r[2]), "=r"(r[3]) : "r"(a));
}
__device__ __forceinline__ void ldmB(unsigned r[2], uint32_t a) {
    asm volatile("ldmatrix.sync.aligned.m8n8.x2.trans.shared.b16 {%0,%1}, [%2];"
                 : "=r"(r[0]), "=r"(r[1]) : "r"(a));
}
__device__ __forceinline__ void mmab(float d[4], const unsigned a[4], const unsigned b[2]) {
    asm volatile(
        "mma.sync.aligned.m16n8k16.row.col.f32.bf16.bf16.f32 "
        "{%0,%1,%2,%3},{%4,%5,%6,%7},{%8,%9},{%0,%1,%2,%3};"
        : "+f"(d[0]), "+f"(d[1]), "+f"(d[2]), "+f"(d[3])
        : "r"(a[0]), "r"(a[1]), "r"(a[2]), "r"(a[3]), "r"(b[0]), "r"(b[1]));
}

__global__ void kdum() {}

// ============================================================================
// k0: transpose + hi/lo-split + pad weights into ldmatrix B images [K][N+pad]
// ============================================================================
__global__ void k0(const float* __restrict__ W1, const float* __restrict__ W2,
                   const float* __restrict__ W3) {
    int i = blockIdx.x * 256 + threadIdx.x;
    float x;
    unsigned short *dh, *dl;
    int idx;
    if (i < 9216) {                       // W1: [128k][64n] -> [128][72]
        int k = i / 72, n = i % 72;
        x = (n < 64) ? W1[k * 64 + n] : 0.f;
        idx = i; dh = gW1hi; dl = gW1lo;
    } else if (i < 50688) {               // W2[kk]: [64k][64n] -> [9][64][72]
        int j = i - 9216;
        int kk = j / 4608, r = j % 4608, ki = r / 72, n = r % 72;
        x = (n < 64) ? W2[kk * 4096 + ki * 64 + n] : 0.f;
        idx = j; dh = gW2hi; dl = gW2lo;
    } else if (i < 59392) {               // W3: [64k][128n] -> [64][136]
        int j = i - 50688;
        int ki = j / 136, n = j % 136;
        x = (n < 128) ? W3[ki * 128 + n] : 0.f;
        idx = j; dh = gW3hi; dl = gW3lo;
    } else return;
    __nv_bfloat16 h = __float2bfloat16(x);
    dh[idx] = __bfloat16_as_ushort(h);
    dl[idx] = __bfloat16_as_ushort(__float2bfloat16(x - __bfloat162float(h)));
}

// ============================================================================
// k1: h = silu(bn1(feat @ W1))  [128 rows/block, 256 thr, warp = 16 rows]
// ============================================================================
#define O_B1HI 0
#define O_B1LO 18432
#define O_A1HI 36864
#define O_A1LO 47104
#define O_P1SC 57344
#define O_P1TB 57600
#define SM1    57856

__global__ __launch_bounds__(256, 3) void k1(
    const float* __restrict__ feat,
    const float* __restrict__ g1, const float* __restrict__ b1,
    const float* __restrict__ m1, const float* __restrict__ v1)
{
    extern __shared__ char sm[];
    uint32_t sb = s2u(sm);
    int t = threadIdx.x, wid = t >> 5, lane = t & 31;
    int base = blockIdx.x * 128;

    for (int q = t; q < 2304; q += 256) {
        if (q < 1152) cpa16(sb + O_B1HI + q * 16, gW1hi + q * 8);
        else          cpa16(sb + O_B1LO + (q - 1152) * 16, gW1lo + (q - 1152) * 8);
    }
    CP_COMMIT();
    if (t < 64) {
        float s = g1[t] * rsqrtf(v1[t] + EPS);
        ((float*)(sm + O_P1SC))[t] = s;
        ((float*)(sm + O_P1TB))[t] = b1[t] - m1[t] * s;
    }

    float d[8][4] = {};
    int arow = ((lane >> 3) & 1) * 8 + (lane & 7);
    int acol = (lane >> 4) * 16;
    int brow = arow;

    for (int kc = 0; kc < 4; kc++) {
        __syncthreads();
        #pragma unroll
        for (int i = 0; i < 4; i++) {
            int idx = t + 256 * i, r = idx >> 3, p = idx & 7;
            int site = base + r;
            float4 f = (site < NS) ? ((const float4*)feat)[(size_t)site * 32 + kc * 8 + p]
                                   : make_float4(0.f, 0.f, 0.f, 0.f);
            unsigned h0, l0, h1, l1;
            split2(f.x, f.y, h0, l0);
            split2(f.z, f.w, h1, l1);
            *(uint2*)(sm + O_A1HI + r * 80 + p * 8) = make_uint2(h0, h1);
            *(uint2*)(sm + O_A1LO + r * 80 + p * 8) = make_uint2(l0, l1);
        }
        CP_WAIT0();
        __syncthreads();
        unsigned ah[2][4], al[2][4];
        #pragma unroll
        for (int kq = 0; kq < 2; kq++) {
            uint32_t a = sb + O_A1HI + (wid * 16 + arow) * 80 + kq * 32 + acol;
            ldmA(ah[kq], a);
            ldmA(al[kq], a + (O_A1LO - O_A1HI));
        }
        #pragma unroll
        for (int n8 = 0; n8 < 8; n8++) {
            unsigned bh[2][2], bl[2][2];
            #pragma unroll
            for (int kq = 0; kq < 2; kq++) {
                uint32_t a = sb + O_B1HI + (kc * 32 + kq * 16 + brow) * 144 + n8 * 16;
                ldmB(bh[kq], a);
                ldmB(bl[kq], a + (O_B1LO - O_B1HI));
            }
            #pragma unroll
            for (int kq = 0; kq < 2; kq++) {
                mmab(d[n8], ah[kq], bh[kq]);
                mmab(d[n8], ah[kq], bl[kq]);
                mmab(d[n8], al[kq], bh[kq]);
            }
        }
    }
    const float* sc = (const float*)(sm + O_P1SC);
    const float* tb = (const float*)(sm + O_P1TB);
    #pragma unroll
    for (int n8 = 0; n8 < 8; n8++) {
        int c = 8 * n8 + 2 * (lane & 3);
        float s0 = sc[c], s1 = sc[c + 1], t0 = tb[c], t1 = tb[c + 1];
        #pragma unroll
        for (int h = 0; h < 2; h++) {
            int site = base + wid * 16 + (lane >> 2) + 8 * h;
            if (site < NS) {
                float o0 = silu(d[n8][2 * h] * s0 + t0);
                float o1 = silu(d[n8][2 * h + 1] * s1 + t1);
                unsigned hw, lw;
                split2(o0, o1, hw, lw);
                g_hhi[(size_t)site * 32 + (c >> 1)] = hw;
                g_hlo[(size_t)site * 32 + (c >> 1)] = lw;
            }
        }
    }
}

// ============================================================================
// k2: 512 threads (32 warps/SM at 2 blocks), 128 sites/block.
// cv2: 64-row double-buffered items, compute split over 16 warps =
// (row-half rg) x (col-group cg). cv3: (col-half) x (row-tile).
// A3 tile placed at G1/W0 (dead post-cv2) to avoid W3-image overlap.
// ============================================================================
#define O_ACC  0           // f32 [128][66] = 33792
#define O_G0   33792       // gather slot 0: hi[64*144] + lo[64*144]
#define O_G1   52224       // gather slot 1
#define O_W0   70656       // W2 slot 0: hi[9216] + lo[9216]
#define O_W1   89088       // W2 slot 1
#define O_LP   107520      // u32 [9][128] packed (id<<8 | row)
#define O_CN   112128      // int [12]
#define O_IT   112176      // int [20]
#define O_NI   112256
#define O_SC2  112288
#define O_TB2  112544
#define O_SC3  112800
#define O_TB3  113312
#define SM2    113856
#define O_A3HI 52224       // post-cv2: A3 tile over G1 (52224..70656)
#define O_A3LO 70656       //           and W0 (70656..89088) - disjoint from W3 images
#define O_W3HI 0           // W3 image over ACC region: 0..17408
#define O_W3LO 17408       //                           17408..34816 (< O_A3HI)

__global__ __launch_bounds__(512, 2) void k2(
    const float* __restrict__ feat, const int* __restrict__ nbr,
    const float* __restrict__ g2, const float* __restrict__ b2,
    const float* __restrict__ m2, const float* __restrict__ v2,
    const float* __restrict__ g3, const float* __restrict__ b3,
    const float* __restrict__ m3, const float* __restrict__ v3,
    float* __restrict__ out)
{
    extern __shared__ char sm[];
    uint32_t sb = s2u(sm);
    int t = threadIdx.x, wid = t >> 5, lane = t & 31;
    int base = blockIdx.x * 128;
    unsigned* lp = (unsigned*)(sm + O_LP);
    int* cnt9 = (int*)(sm + O_CN);
    int* items = (int*)(sm + O_IT);
    float* acc = (float*)(sm + O_ACC);

    if (t < 64) {
        float s = g2[t] * rsqrtf(v2[t] + EPS);
        ((float*)(sm + O_SC2))[t] = s;
        ((float*)(sm + O_TB2))[t] = b2[t] - m2[t] * s;
    }
    if (t < 128) {
        float s = g3[t] * rsqrtf(v3[t] + EPS);
        ((float*)(sm + O_SC3))[t] = s;
        ((float*)(sm + O_TB3))[t] = b3[t] - m3[t] * s;
    }
    for (int q = t; q < 128 * 66; q += 512) acc[q] = 0.f;

    // compaction: warps 0..8, one offset each
    if (wid < 9) {
        int k = wid;
        int cbase = 0;
        #pragma unroll
        for (int g = 0; g < 4; g++) {
            int site = base + g * 32 + lane;
            int id = (site < NS) ? __ldg(&nbr[(size_t)k * NS + site]) : NS;
            bool val = id < NS;
            unsigned msk = __ballot_sync(0xffffffffu, val);
            if (val) {
                int p = cbase + __popc(msk & ((1u << lane) - 1u));
                lp[k * 128 + p] = ((unsigned)id << 8) | (g * 32 + lane);
            }
            cbase += __popc(msk);
        }
        if (lane == 0) cnt9[k] = cbase;
    }
    __syncthreads();
    if (t == 0) {
        int ni = 0;
        for (int k = 0; k < 9; k++)
            for (int c0 = 0; c0 < cnt9[k]; c0 += 64)
                items[ni++] = (k << 1) | (c0 >> 6);
        *(int*)(sm + O_NI) = ni;
    }
    __syncthreads();
    int nitems = *(int*)(sm + O_NI);

    auto issue_item = [&](int j) {
        int pk = items[j];
        int kk = pk >> 1, c0 = (pk & 1) << 6;
        int chunk = min(cnt9[kk] - c0, 64);
        uint32_t gb = sb + ((j & 1) ? O_G1 : O_G0);
        for (int q = t; q < chunk * 16; q += 512) {
            int r = q >> 4, s = q & 15;
            unsigned id = lp[kk * 128 + c0 + r] >> 8;
            if (s < 8) cpa16(gb + r * 144 + s * 16, g_hhi + (size_t)id * 32 + s * 4);
            else       cpa16(gb + 9216 + r * 144 + (s - 8) * 16, g_hlo + (size_t)id * 32 + (s - 8) * 4);
        }
        uint32_t wbuf = sb + ((j & 1) ? O_W1 : O_W0);
        for (int q = t; q < 1152; q += 512) {
            if (q < 576) cpa16(wbuf + q * 16, gW2hi + kk * 4608 + q * 8);
            else         cpa16(wbuf + 9216 + (q - 576) * 16, gW2lo + kk * 4608 + (q - 576) * 8);
        }
    };

    int arow = ((lane >> 3) & 1) * 8 + (lane & 7);
    int acol = (lane >> 4) * 16;
    int brow = arow;
    int cg = wid & 7;     // cv2 col group (8 cols)
    int rg = wid >> 3;    // cv2 row-half: tiles rg, rg+2, ...

    issue_item(0);
    CP_COMMIT();

    for (int it = 0; it < nitems; it++) {
        __syncthreads();
        if (it + 1 < nitems) issue_item(it + 1);
        CP_COMMIT();
        if (it + 1 < nitems) CP_WAIT1(); else CP_WAIT0();
        __syncthreads();

        int pk = items[it];
        int kk = pk >> 1, c0 = (pk & 1) << 6;
        int chunk = min(cnt9[kk] - c0, 64);
        uint32_t gb = sb + ((it & 1) ? O_G1 : O_G0);
        uint32_t wbuf = sb + ((it & 1) ? O_W1 : O_W0);
        int mtiles = (chunk + 15) >> 4;

        unsigned bhf[4][2], blf[4][2];
        #pragma unroll
        for (int kq = 0; kq < 4; kq++) {
            uint32_t a = wbuf + (kq * 16 + brow) * 144 + cg * 16;
            ldmB(bhf[kq], a);
            ldmB(blf[kq], a + 9216);
        }
        for (int mt = rg; mt < mtiles; mt += 2) {
            float dd[4] = {};
            unsigned ah[4], al[4];
            #pragma unroll
            for (int kq = 0; kq < 4; kq++) {
                uint32_t a = gb + (mt * 16 + arow) * 144 + kq * 32 + acol;
                ldmA(ah, a);
                ldmA(al, a + 9216);
                mmab(dd, ah, bhf[kq]);
                mmab(dd, ah, blf[kq]);
                mmab(dd, al, bhf[kq]);
            }
            int c = 8 * cg + 2 * (lane & 3);
            #pragma unroll
            for (int h = 0; h < 2; h++) {
                int gr = mt * 16 + (lane >> 2) + 8 * h;
                if (gr < chunk) {
                    int rw = lp[kk * 128 + c0 + gr] & 255;
                    float2* ap = (float2*)(acc + rw * 66 + c);
                    float2 v = *ap;
                    v.x += dd[2 * h]; v.y += dd[2 * h + 1];
                    *ap = v;
                }
            }
        }
    }
    __syncthreads();
    // BN2 + SiLU -> split bf16 A3 tile (over G1/W0, clear of W3 images)
    const float* sc2 = (const float*)(sm + O_SC2);
    const float* tb2 = (const float*)(sm + O_TB2);
    #pragma unroll
    for (int i = 0; i < 8; i++) {
        int idx = t + 512 * i, r = idx >> 5, p = idx & 31;
        float x0 = acc[r * 66 + 2 * p] * sc2[2 * p] + tb2[2 * p];
        float x1 = acc[r * 66 + 2 * p + 1] * sc2[2 * p + 1] + tb2[2 * p + 1];
        x0 = silu(x0); x1 = silu(x1);
        unsigned hw, lw;
        split2(x0, x1, hw, lw);
        *(unsigned*)(sm + O_A3HI + r * 144 + p * 4) = hw;
        *(unsigned*)(sm + O_A3LO + r * 144 + p * 4) = lw;
    }
    __syncthreads();   // ACC reads done before W3 overwrites it
    for (int q = t; q < 2176; q += 512) {
        if (q < 1088) cpa16(sb + O_W3HI + q * 16, gW3hi + q * 8);
        else          cpa16(sb + O_W3LO + (q - 1088) * 16, gW3lo + (q - 1088) * 8);
    }
    CP_COMMIT();
    CP_WAIT0();
    __syncthreads();
    // cv3: warp = (ch col-half) x (rt row-tile of 16)
    const float* sc3 = (const float*)(sm + O_SC3);
    const float* tb3 = (const float*)(sm + O_TB3);
    int ch = wid >> 3, rt = wid & 7;
    unsigned ah[4][4], al[4][4];
    #pragma unroll
    for (int kq = 0; kq < 4; kq++) {
        uint32_t a = sb + O_A3HI + (rt * 16 + arow) * 144 + kq * 32 + acol;
        ldmA(ah[kq], a);
        ldmA(al[kq], a + (O_A3LO - O_A3HI));
    }
    #pragma unroll
    for (int n8 = 0; n8 < 8; n8++) {
        unsigned b_h[4][2], b_l[4][2];
        #pragma unroll
        for (int kq = 0; kq < 4; kq++) {
            uint32_t a = sb + O_W3HI + (kq * 16 + brow) * 272 + ch * 128 + n8 * 16;
            ldmB(b_h[kq], a);
            ldmB(b_l[kq], a + (O_W3LO - O_W3HI));
        }
        float dd[4] = {};
        #pragma unroll
        for (int kq = 0; kq < 4; kq++) {
            mmab(dd, ah[kq], b_h[kq]);
            mmab(dd, ah[kq], b_l[kq]);
            mmab(dd, al[kq], b_h[kq]);
        }
        int c = ch * 64 + n8 * 8 + 2 * (lane & 3);
        float s0 = sc3[c], s1 = sc3[c + 1], t0 = tb3[c], t1 = tb3[c + 1];
        #pragma unroll
        for (int h = 0; h < 2; h++) {
            int site = base + rt * 16 + (lane >> 2) + 8 * h;
            if (site < NS) {
                float2 f = *(const float2*)(feat + (size_t)site * 128 + c);
                float o0 = silu(dd[2 * h] * s0 + t0 + f.x);
                float o1 = silu(dd[2 * h + 1] * s1 + t1 + f.y);
                *(float2*)(out + (size_t)site * 128 + c) = make_float2(o0, o1);
            }
        }
    }
}

// ============================================================================
extern "C" void kernel_launch(void* const* d_in, const int* in_sizes, int n_in,
                              void* d_out, int out_size) {
    const float* feat = (const float*)d_in[0];
    const int*   nbr  = (const int*)d_in[1];
    const float* W1 = (const float*)d_in[2];
    const float* W2 = (const float*)d_in[3];
    const float* W3 = (const float*)d_in[4];
    const float* g1 = (const float*)d_in[5];
    const float* b1 = (const float*)d_in[6];
    const float* m1 = (const float*)d_in[7];
    const float* v1 = (const float*)d_in[8];
    const float* g2 = (const float*)d_in[9];
    const float* b2 = (const float*)d_in[10];
    const float* m2 = (const float*)d_in[11];
    const float* v2 = (const float*)d_in[12];
    const float* g3 = (const float*)d_in[13];
    const float* b3 = (const float*)d_in[14];
    const float* m3 = (const float*)d_in[15];
    const float* v3 = (const float*)d_in[16];
    float* out = (float*)d_out;

    cudaFuncSetAttribute(k1, cudaFuncAttributeMaxDynamicSharedMemorySize, SM1);
    cudaFuncSetAttribute(k2, cudaFuncAttributeMaxDynamicSharedMemorySize, SM2);

    int grid = (NS + 127) / 128;   // 3907
    kdum<<<1, 32>>>();
    k0<<<232, 256>>>(W1, W2, W3);
    k1<<<grid, 256, SM1>>>(feat, g1, b1, m1, v1);
    k2<<<grid, 512, SM2>>>(feat, nbr, g2, b2, m2, v2, g3, b3, m3, v3, out);
}

// round 16
// speedup vs baseline: 1.6146x; 1.1528x over previous
#include <cuda_runtime.h>
#include <cuda_bf16.h>
#include <cstdint>

#define NS 500000
#define EPS 1e-5f

// RN-bf16 hidden activations: 2 channels packed per u32, 32 u32 per site
__device__ __align__(16) unsigned g_h[NS * 32];
// padded ldmatrix-ready weight images: [K][N+pad] u16, built by k0 (hi/lo split)
__device__ __align__(16) unsigned short gW1hi[128 * 72], gW1lo[128 * 72];
__device__ __align__(16) unsigned short gW2hi[9 * 64 * 72], gW2lo[9 * 64 * 72];
__device__ __align__(16) unsigned short gW3hi[64 * 136], gW3lo[64 * 136];

__device__ __forceinline__ uint32_t s2u(const void* p) {
    uint32_t a;
    asm("{ .reg .u64 t; cvta.to.shared.u64 t, %1; cvt.u32.u64 %0, t; }" : "=r"(a) : "l"(p));
    return a;
}
__device__ __forceinline__ float silu(float x) { return x / (1.0f + __expf(-x)); }
// truncation split (for cv1's 3-pass A): hi = top 16 bits, lo = rn(x - hi)
__device__ __forceinline__ void split2(float x0, float x1, unsigned& hi, unsigned& lo) {
    unsigned u0 = __float_as_uint(x0), u1 = __float_as_uint(x1);
    asm("prmt.b32 %0, %1, %2, 0x7632;" : "=r"(hi) : "r"(u0), "r"(u1));
    float l0 = x0 - __uint_as_float(u0 & 0xffff0000u);
    float l1 = x1 - __uint_as_float(u1 & 0xffff0000u);
    asm("cvt.rn.bf16x2.f32 %0, %1, %2;" : "=r"(lo) : "f"(l1), "f"(l0));
}
// round-to-nearest bf16 pair pack (x0 -> low half, x1 -> high half)
__device__ __forceinline__ unsigned rn2(float x0, float x1) {
    unsigned r;
    asm("cvt.rn.bf16x2.f32 %0, %1, %2;" : "=r"(r) : "f"(x1), "f"(x0));
    return r;
}
__device__ __forceinline__ void cpa16(uint32_t dst, const void* src) {
    asm volatile("cp.async.ca.shared.global [%0], [%1], 16;" :: "r"(dst), "l"(src));
}
#define CP_COMMIT() asm volatile("cp.async.commit_group;" ::: "memory")
#define CP_WAIT0()  asm volatile("cp.async.wait_group 0;" ::: "memory")
#define CP_WAIT1()  asm volatile("cp.async.wait_group 1;" ::: "memory")
__device__ __forceinline__ void ldmA(unsigned r[4], uint32_t a) {
    asm volatile("ldmatrix.sync.aligned.m8n8.x4.shared.b16 {%0,%1,%2,%3}, [%4];"
                 : "=r"(r[0]), "=r"(r[1]), "=r"(r[2]), "=r"(r[3]) : "r"(a));
}
__device__ __forceinline__ void ldmB(unsigned r[2], uint32_t a) {
    asm volatile("ldmatrix.sync.aligned.m8n8.x2.trans.shared.b16 {%0,%1}, [%2];"
                 : "=r"(r[0]), "=r"(r[1]) : "r"(a));
}
__device__ __forceinline__ void mmab(float d[4], const unsigned a[4], const unsigned b[2]) {
    asm volatile(
        "mma.sync.aligned.m16n8k16.row.col.f32.bf16.bf16.f32 "
        "{%0,%1,%2,%3},{%4,%5,%6,%7},{%8,%9},{%0,%1,%2,%3};"
        : "+f"(d[0]), "+f"(d[1]), "+f"(d[2]), "+f"(d[3])
        : "r"(a[0]), "r"(a[1]), "r"(a[2]), "r"(a[3]), "r"(b[0]), "r"(b[1]));
}

__global__ void kdum() {}

// ============================================================================
// k0: transpose + hi/lo-split + pad weights into ldmatrix B images [K][N+pad]
// ============================================================================
__global__ void k0(const float* __restrict__ W1, const float* __restrict__ W2,
                   const float* __restrict__ W3) {
    int i = blockIdx.x * 256 + threadIdx.x;
    float x;
    unsigned short *dh, *dl;
    int idx;
    if (i < 9216) {                       // W1: [128k][64n] -> [128][72]
        int k = i / 72, n = i % 72;
        x = (n < 64) ? W1[k * 64 + n] : 0.f;
        idx = i; dh = gW1hi; dl = gW1lo;
    } else if (i < 50688) {               // W2[kk]: [64k][64n] -> [9][64][72]
        int j = i - 9216;
        int kk = j / 4608, r = j % 4608, ki = r / 72, n = r % 72;
        x = (n < 64) ? W2[kk * 4096 + ki * 64 + n] : 0.f;
        idx = j; dh = gW2hi; dl = gW2lo;
    } else if (i < 59392) {               // W3: [64k][128n] -> [64][136]
        int j = i - 50688;
        int ki = j / 136, n = j % 136;
        x = (n < 128) ? W3[ki * 128 + n] : 0.f;
        idx = j; dh = gW3hi; dl = gW3lo;
    } else return;
    __nv_bfloat16 h = __float2bfloat16(x);
    dh[idx] = __bfloat16_as_ushort(h);
    dl[idx] = __bfloat16_as_ushort(__float2bfloat16(x - __bfloat162float(h)));
}

// ============================================================================
// k1: h = silu(bn1(feat @ W1))  [128 rows/block, 256 thr, warp = 16 rows]
// cv1 keeps 3-pass split-A; h stored single RN bf16.
// ============================================================================
#define O_B1HI 0
#define O_B1LO 18432
#define O_A1HI 36864
#define O_A1LO 47104
#define O_P1SC 57344
#define O_P1TB 57600
#define SM1    57856

__global__ __launch_bounds__(256, 3) void k1(
    const float* __restrict__ feat,
    const float* __restrict__ g1, const float* __restrict__ b1,
    const float* __restrict__ m1, const float* __restrict__ v1)
{
    extern __shared__ char sm[];
    uint32_t sb = s2u(sm);
    int t = threadIdx.x, wid = t >> 5, lane = t & 31;
    int base = blockIdx.x * 128;

    for (int q = t; q < 2304; q += 256) {
        if (q < 1152) cpa16(sb + O_B1HI + q * 16, gW1hi + q * 8);
        else          cpa16(sb + O_B1LO + (q - 1152) * 16, gW1lo + (q - 1152) * 8);
    }
    CP_COMMIT();
    if (t < 64) {
        float s = g1[t] * rsqrtf(v1[t] + EPS);
        ((float*)(sm + O_P1SC))[t] = s;
        ((float*)(sm + O_P1TB))[t] = b1[t] - m1[t] * s;
    }

    float d[8][4] = {};
    int arow = ((lane >> 3) & 1) * 8 + (lane & 7);
    int acol = (lane >> 4) * 16;
    int brow = arow;

    for (int kc = 0; kc < 4; kc++) {
        __syncthreads();
        #pragma unroll
        for (int i = 0; i < 4; i++) {
            int idx = t + 256 * i, r = idx >> 3, p = idx & 7;
            int site = base + r;
            float4 f = (site < NS) ? ((const float4*)feat)[(size_t)site * 32 + kc * 8 + p]
                                   : make_float4(0.f, 0.f, 0.f, 0.f);
            unsigned h0, l0, h1, l1;
            split2(f.x, f.y, h0, l0);
            split2(f.z, f.w, h1, l1);
            *(uint2*)(sm + O_A1HI + r * 80 + p * 8) = make_uint2(h0, h1);
            *(uint2*)(sm + O_A1LO + r * 80 + p * 8) = make_uint2(l0, l1);
        }
        CP_WAIT0();
        __syncthreads();
        unsigned ah[2][4], al[2][4];
        #pragma unroll
        for (int kq = 0; kq < 2; kq++) {
            uint32_t a = sb + O_A1HI + (wid * 16 + arow) * 80 + kq * 32 + acol;
            ldmA(ah[kq], a);
            ldmA(al[kq], a + (O_A1LO - O_A1HI));
        }
        #pragma unroll
        for (int n8 = 0; n8 < 8; n8++) {
            unsigned bh[2][2], bl[2][2];
            #pragma unroll
            for (int kq = 0; kq < 2; kq++) {
                uint32_t a = sb + O_B1HI + (kc * 32 + kq * 16 + brow) * 144 + n8 * 16;
                ldmB(bh[kq], a);
                ldmB(bl[kq], a + (O_B1LO - O_B1HI));
            }
            #pragma unroll
            for (int kq = 0; kq < 2; kq++) {
                mmab(d[n8], ah[kq], bh[kq]);
                mmab(d[n8], ah[kq], bl[kq]);
                mmab(d[n8], al[kq], bh[kq]);
            }
        }
    }
    const float* sc = (const float*)(sm + O_P1SC);
    const float* tb = (const float*)(sm + O_P1TB);
    #pragma unroll
    for (int n8 = 0; n8 < 8; n8++) {
        int c = 8 * n8 + 2 * (lane & 3);
        float s0 = sc[c], s1 = sc[c + 1], t0 = tb[c], t1 = tb[c + 1];
        #pragma unroll
        for (int h = 0; h < 2; h++) {
            int site = base + wid * 16 + (lane >> 2) + 8 * h;
            if (site < NS) {
                float o0 = silu(d[n8][2 * h] * s0 + t0);
                float o1 = silu(d[n8][2 * h + 1] * s1 + t1);
                g_h[(size_t)site * 32 + (c >> 1)] = rn2(o0, o1);
            }
        }
    }
}

// ============================================================================
// k2: 512 threads, 128 sites/block. cv2: single-RN-A x split-B (2 MMA/kq),
// 64-row double-buffered items, 16 compute warps = (row-half) x (col-group).
// cv3: same 2-pass scheme, (col-half) x (row-tile).
// ============================================================================
#define O_ACC  0           // f32 [128][66] = 33792
#define O_G0   33792       // gather slot 0: 64*144 = 9216 (RN bf16)
#define O_G1   43008       // gather slot 1
#define O_W0   52224       // W2 slot 0: hi[9216] + lo[9216] = 18432
#define O_W1   70656       // W2 slot 1
#define O_LP   89088       // u32 [9][128] packed (id<<8 | row)
#define O_CN   93696       // int [12]
#define O_IT   93744       // int [20]
#define O_NI   93824
#define O_SC2  93840
#define O_TB2  94096
#define O_SC3  94352
#define O_TB3  94864
#define SM2    95488
#define O_A3   52224       // post-cv2: A3 tile (128*144 = 18432) over W2 slots
#define O_W3HI 0           // W3 image over ACC/G0 region: 0..17408
#define O_W3LO 17408       //                              17408..34816 (dead post-cv2)

__global__ __launch_bounds__(512, 2) void k2(
    const float* __restrict__ feat, const int* __restrict__ nbr,
    const float* __restrict__ g2, const float* __restrict__ b2,
    const float* __restrict__ m2, const float* __restrict__ v2,
    const float* __restrict__ g3, const float* __restrict__ b3,
    const float* __restrict__ m3, const float* __restrict__ v3,
    float* __restrict__ out)
{
    extern __shared__ char sm[];
    uint32_t sb = s2u(sm);
    int t = threadIdx.x, wid = t >> 5, lane = t & 31;
    int base = blockIdx.x * 128;
    unsigned* lp = (unsigned*)(sm + O_LP);
    int* cnt9 = (int*)(sm + O_CN);
    int* items = (int*)(sm + O_IT);
    float* acc = (float*)(sm + O_ACC);

    if (t < 64) {
        float s = g2[t] * rsqrtf(v2[t] + EPS);
        ((float*)(sm + O_SC2))[t] = s;
        ((float*)(sm + O_TB2))[t] = b2[t] - m2[t] * s;
    }
    if (t < 128) {
        float s = g3[t] * rsqrtf(v3[t] + EPS);
        ((float*)(sm + O_SC3))[t] = s;
        ((float*)(sm + O_TB3))[t] = b3[t] - m3[t] * s;
    }
    for (int q = t; q < 128 * 66; q += 512) acc[q] = 0.f;

    // compaction: warps 0..8, one offset each
    if (wid < 9) {
        int k = wid;
        int cbase = 0;
        #pragma unroll
        for (int g = 0; g < 4; g++) {
            int site = base + g * 32 + lane;
            int id = (site < NS) ? __ldg(&nbr[(size_t)k * NS + site]) : NS;
            bool val = id < NS;
            unsigned msk = __ballot_sync(0xffffffffu, val);
            if (val) {
                int p = cbase + __popc(msk & ((1u << lane) - 1u));
                lp[k * 128 + p] = ((unsigned)id << 8) | (g * 32 + lane);
            }
            cbase += __popc(msk);
        }
        if (lane == 0) cnt9[k] = cbase;
    }
    __syncthreads();
    if (t == 0) {
        int ni = 0;
        for (int k = 0; k < 9; k++)
            for (int c0 = 0; c0 < cnt9[k]; c0 += 64)
                items[ni++] = (k << 1) | (c0 >> 6);
        *(int*)(sm + O_NI) = ni;
    }
    __syncthreads();
    int nitems = *(int*)(sm + O_NI);

    auto issue_item = [&](int j) {
        int pk = items[j];
        int kk = pk >> 1, c0 = (pk & 1) << 6;
        int chunk = min(cnt9[kk] - c0, 64);
        uint32_t gb = sb + ((j & 1) ? O_G1 : O_G0);
        for (int q = t; q < chunk * 8; q += 512) {
            int r = q >> 3, s = q & 7;
            unsigned id = lp[kk * 128 + c0 + r] >> 8;
            cpa16(gb + r * 144 + s * 16, g_h + (size_t)id * 32 + s * 4);
        }
        uint32_t wbuf = sb + ((j & 1) ? O_W1 : O_W0);
        for (int q = t; q < 1152; q += 512) {
            if (q < 576) cpa16(wbuf + q * 16, gW2hi + kk * 4608 + q * 8);
            else         cpa16(wbuf + 9216 + (q - 576) * 16, gW2lo + kk * 4608 + (q - 576) * 8);
        }
    };

    int arow = ((lane >> 3) & 1) * 8 + (lane & 7);
    int acol = (lane >> 4) * 16;
    int brow = arow;
    int cg = wid & 7;     // cv2 col group (8 cols)
    int rg = wid >> 3;    // cv2 row-half: tiles rg, rg+2, ...

    issue_item(0);
    CP_COMMIT();

    for (int it = 0; it < nitems; it++) {
        __syncthreads();
        if (it + 1 < nitems) issue_item(it + 1);
        CP_COMMIT();
        if (it + 1 < nitems) CP_WAIT1(); else CP_WAIT0();
        __syncthreads();

        int pk = items[it];
        int kk = pk >> 1, c0 = (pk & 1) << 6;
        int chunk = min(cnt9[kk] - c0, 64);
        uint32_t gb = sb + ((it & 1) ? O_G1 : O_G0);
        uint32_t wbuf = sb + ((it & 1) ? O_W1 : O_W0);
        int mtiles = (chunk + 15) >> 4;

        unsigned bhf[4][2], blf[4][2];
        #pragma unroll
        for (int kq = 0; kq < 4; kq++) {
            uint32_t a = wbuf + (kq * 16 + brow) * 144 + cg * 16;
            ldmB(bhf[kq], a);
            ldmB(blf[kq], a + 9216);
        }
        for (int mt = rg; mt < mtiles; mt += 2) {
            float dd[4] = {};
            unsigned ah[4];
            #pragma unroll
            for (int kq = 0; kq < 4; kq++) {
                ldmA(ah, gb + (mt * 16 + arow) * 144 + kq * 32 + acol);
                mmab(dd, ah, bhf[kq]);
                mmab(dd, ah, blf[kq]);
            }
            int c = 8 * cg + 2 * (lane & 3);
            #pragma unroll
            for (int h = 0; h < 2; h++) {
                int gr = mt * 16 + (lane >> 2) + 8 * h;
                if (gr < chunk) {
                    int rw = lp[kk * 128 + c0 + gr] & 255;
                    float2* ap = (float2*)(acc + rw * 66 + c);
                    float2 v = *ap;
                    v.x += dd[2 * h]; v.y += dd[2 * h + 1];
                    *ap = v;
                }
            }
        }
    }
    __syncthreads();
    // BN2 + SiLU -> RN bf16 A3 tile (over W2 slots, clear of W3 images)
    const float* sc2 = (const float*)(sm + O_SC2);
    const float* tb2 = (const float*)(sm + O_TB2);
    #pragma unroll
    for (int i = 0; i < 8; i++) {
        int idx = t + 512 * i, r = idx >> 5, p = idx & 31;
        float x0 = acc[r * 66 + 2 * p] * sc2[2 * p] + tb2[2 * p];
        float x1 = acc[r * 66 + 2 * p + 1] * sc2[2 * p + 1] + tb2[2 * p + 1];
        *(unsigned*)(sm + O_A3 + r * 144 + p * 4) = rn2(silu(x0), silu(x1));
    }
    __syncthreads();   // ACC reads done before W3 overwrites it
    for (int q = t; q < 2176; q += 512) {
        if (q < 1088) cpa16(sb + O_W3HI + q * 16, gW3hi + q * 8);
        else          cpa16(sb + O_W3LO + (q - 1088) * 16, gW3lo + (q - 1088) * 8);
    }
    CP_COMMIT();
    CP_WAIT0();
    __syncthreads();
    // cv3: warp = (ch col-half) x (rt row-tile of 16), 2-pass (Bh + Bl)
    const float* sc3 = (const float*)(sm + O_SC3);
    const float* tb3 = (const float*)(sm + O_TB3);
    int ch = wid >> 3, rt = wid & 7;
    unsigned ah[4][4];
    #pragma unroll
    for (int kq = 0; kq < 4; kq++)
        ldmA(ah[kq], sb + O_A3 + (rt * 16 + arow) * 144 + kq * 32 + acol);
    #pragma unroll
    for (int n8 = 0; n8 < 8; n8++) {
        unsigned b_h[4][2], b_l[4][2];
        #pragma unroll
        for (int kq = 0; kq < 4; kq++) {
            uint32_t a = sb + O_W3HI + (kq * 16 + brow) * 272 + ch * 128 + n8 * 16;
            ldmB(b_h[kq], a);
            ldmB(b_l[kq], a + (O_W3LO - O_W3HI));
        }
        float dd[4] = {};
        #pragma unroll
        for (int kq = 0; kq < 4; kq++) {
            mmab(dd, ah[kq], b_h[kq]);
            mmab(dd, ah[kq], b_l[kq]);
        }
        int c = ch * 64 + n8 * 8 + 2 * (lane & 3);
        float s0 = sc3[c], s1 = sc3[c + 1], t0 = tb3[c], t1 = tb3[c + 1];
        #pragma unroll
        for (int h = 0; h < 2; h++) {
            int site = base + rt * 16 + (lane >> 2) + 8 * h;
            if (site < NS) {
                float2 f = *(const float2*)(feat + (size_t)site * 128 + c);
                float o0 = silu(dd[2 * h] * s0 + t0 + f.x);
                float o1 = silu(dd[2 * h + 1] * s1 + t1 + f.y);
                *(float2*)(out + (size_t)site * 128 + c) = make_float2(o0, o1);
            }
        }
    }
}

// ============================================================================
extern "C" void kernel_launch(void* const* d_in, const int* in_sizes, int n_in,
                              void* d_out, int out_size) {
    const float* feat = (const float*)d_in[0];
    const int*   nbr  = (const int*)d_in[1];
    const float* W1 = (const float*)d_in[2];
    const float* W2 = (const float*)d_in[3];
    const float* W3 = (const float*)d_in[4];
    const float* g1 = (const float*)d_in[5];
    const float* b1 = (const float*)d_in[6];
    const float* m1 = (const float*)d_in[7];
    const float* v1 = (const float*)d_in[8];
    const float* g2 = (const float*)d_in[9];
    const float* b2 = (const float*)d_in[10];
    const float* m2 = (const float*)d_in[11];
    const float* v2 = (const float*)d_in[12];
    const float* g3 = (const float*)d_in[13];
    const float* b3 = (const float*)d_in[14];
    const float* m3 = (const float*)d_in[15];
    const float* v3 = (const float*)d_in[16];
    float* out = (float*)d_out;

    cudaFuncSetAttribute(k1, cudaFuncAttributeMaxDynamicSharedMemorySize, SM1);
    cudaFuncSetAttribute(k2, cudaFuncAttributeMaxDynamicSharedMemorySize, SM2);

    int grid = (NS + 127) / 128;   // 3907
    kdum<<<1, 32>>>();
    k0<<<232, 256>>>(W1, W2, W3);
    k1<<<grid, 256, SM1>>>(feat, g1, b1, m1, v1);
    k2<<<grid, 512, SM2>>>(feat, nbr, g2, b2, m2, v2, g3, b3, m3, v3, out);
}

// round 17
// speedup vs baseline: 1.7821x; 1.1037x over previous
#include <cuda_runtime.h>
#include <cuda_bf16.h>
#include <cstdint>

#define NS 500000
#define EPS 1e-5f

// RN-bf16 hidden activations: 2 channels packed per u32, 32 u32 per site
__device__ __align__(16) unsigned g_h[NS * 32];
// W1: split hi/lo ldmatrix images [128][72]; W2/W3: single RN images
__device__ __align__(16) unsigned short gW1hi[128 * 72], gW1lo[128 * 72];
__device__ __align__(16) unsigned short gW2r[9 * 64 * 72];
__device__ __align__(16) unsigned short gW3r[64 * 136];

__device__ __forceinline__ uint32_t s2u(const void* p) {
    uint32_t a;
    asm("{ .reg .u64 t; cvta.to.shared.u64 t, %1; cvt.u32.u64 %0, t; }" : "=r"(a) : "l"(p));
    return a;
}
__device__ __forceinline__ float silu(float x) { return x / (1.0f + __expf(-x)); }
__device__ __forceinline__ void split2(float x0, float x1, unsigned& hi, unsigned& lo) {
    unsigned u0 = __float_as_uint(x0), u1 = __float_as_uint(x1);
    asm("prmt.b32 %0, %1, %2, 0x7632;" : "=r"(hi) : "r"(u0), "r"(u1));
    float l0 = x0 - __uint_as_float(u0 & 0xffff0000u);
    float l1 = x1 - __uint_as_float(u1 & 0xffff0000u);
    asm("cvt.rn.bf16x2.f32 %0, %1, %2;" : "=r"(lo) : "f"(l1), "f"(l0));
}
__device__ __forceinline__ unsigned rn2(float x0, float x1) {
    unsigned r;
    asm("cvt.rn.bf16x2.f32 %0, %1, %2;" : "=r"(r) : "f"(x1), "f"(x0));
    return r;
}
__device__ __forceinline__ void cpa16(uint32_t dst, const void* src) {
    asm volatile("cp.async.ca.shared.global [%0], [%1], 16;" :: "r"(dst), "l"(src));
}
#define CP_COMMIT() asm volatile("cp.async.commit_group;" ::: "memory")
#define CP_WAIT0()  asm volatile("cp.async.wait_group 0;" ::: "memory")
#define CP_WAIT1()  asm volatile("cp.async.wait_group 1;" ::: "memory")
__device__ __forceinline__ void ldmA(unsigned r[4], uint32_t a) {
    asm volatile("ldmatrix.sync.aligned.m8n8.x4.shared.b16 {%0,%1,%2,%3}, [%4];"
                 : "=r"(r[0]), "=r"(r[1]), "=r"(r[2]), "=r"(r[3]) : "r"(a));
}
__device__ __forceinline__ void ldmB(unsigned r[2], uint32_t a) {
    asm volatile("ldmatrix.sync.aligned.m8n8.x2.trans.shared.b16 {%0,%1}, [%2];"
                 : "=r"(r[0]), "=r"(r[1]) : "r"(a));
}
__device__ __forceinline__ void mmab(float d[4], const unsigned a[4], const unsigned b[2]) {
    asm volatile(
        "mma.sync.aligned.m16n8k16.row.col.f32.bf16.bf16.f32 "
        "{%0,%1,%2,%3},{%4,%5,%6,%7},{%8,%9},{%0,%1,%2,%3};"
        : "+f"(d[0]), "+f"(d[1]), "+f"(d[2]), "+f"(d[3])
        : "r"(a[0]), "r"(a[1]), "r"(a[2]), "r"(a[3]), "r"(b[0]), "r"(b[1]));
}

__global__ void kdum() {}

// ============================================================================
// k0: W1 -> split hi/lo images; W2/W3 -> single RN images
// ============================================================================
__global__ void k0(const float* __restrict__ W1, const float* __restrict__ W2,
                   const float* __restrict__ W3) {
    int i = blockIdx.x * 256 + threadIdx.x;
    if (i < 9216) {                       // W1: [128k][64n] -> [128][72] split
        int k = i / 72, n = i % 72;
        float x = (n < 64) ? W1[k * 64 + n] : 0.f;
        __nv_bfloat16 h = __float2bfloat16(x);
        gW1hi[i] = __bfloat16_as_ushort(h);
        gW1lo[i] = __bfloat16_as_ushort(__float2bfloat16(x - __bfloat162float(h)));
    } else if (i < 50688) {               // W2[kk]: [64k][64n] -> [9][64][72] RN
        int j = i - 9216;
        int kk = j / 4608, r = j % 4608, ki = r / 72, n = r % 72;
        float x = (n < 64) ? W2[kk * 4096 + ki * 64 + n] : 0.f;
        gW2r[j] = __bfloat16_as_ushort(__float2bfloat16(x));
    } else if (i < 59392) {               // W3: [64k][128n] -> [64][136] RN
        int j = i - 50688;
        int ki = j / 136, n = j % 136;
        float x = (n < 128) ? W3[ki * 128 + n] : 0.f;
        gW3r[j] = __bfloat16_as_ushort(__float2bfloat16(x));
    }
}

// ============================================================================
// k1: h = silu(bn1(feat @ W1))  [128 rows/block, 256 thr] - split-A 3-pass
// ============================================================================
#define O_B1HI 0
#define O_B1LO 18432
#define O_A1HI 36864
#define O_A1LO 47104
#define O_P1SC 57344
#define O_P1TB 57600
#define SM1    57856

__global__ __launch_bounds__(256, 3) void k1(
    const float* __restrict__ feat,
    const float* __restrict__ g1, const float* __restrict__ b1,
    const float* __restrict__ m1, const float* __restrict__ v1)
{
    extern __shared__ char sm[];
    uint32_t sb = s2u(sm);
    int t = threadIdx.x, wid = t >> 5, lane = t & 31;
    int base = blockIdx.x * 128;

    for (int q = t; q < 2304; q += 256) {
        if (q < 1152) cpa16(sb + O_B1HI + q * 16, gW1hi + q * 8);
        else          cpa16(sb + O_B1LO + (q - 1152) * 16, gW1lo + (q - 1152) * 8);
    }
    CP_COMMIT();
    if (t < 64) {
        float s = g1[t] * rsqrtf(v1[t] + EPS);
        ((float*)(sm + O_P1SC))[t] = s;
        ((float*)(sm + O_P1TB))[t] = b1[t] - m1[t] * s;
    }

    float d[8][4] = {};
    int arow = ((lane >> 3) & 1) * 8 + (lane & 7);
    int acol = (lane >> 4) * 16;
    int brow = arow;

    for (int kc = 0; kc < 4; kc++) {
        __syncthreads();
        #pragma unroll
        for (int i = 0; i < 4; i++) {
            int idx = t + 256 * i, r = idx >> 3, p = idx & 7;
            int site = base + r;
            float4 f = (site < NS) ? ((const float4*)feat)[(size_t)site * 32 + kc * 8 + p]
                                   : make_float4(0.f, 0.f, 0.f, 0.f);
            unsigned h0, l0, h1, l1;
            split2(f.x, f.y, h0, l0);
            split2(f.z, f.w, h1, l1);
            *(uint2*)(sm + O_A1HI + r * 80 + p * 8) = make_uint2(h0, h1);
            *(uint2*)(sm + O_A1LO + r * 80 + p * 8) = make_uint2(l0, l1);
        }
        CP_WAIT0();
        __syncthreads();
        unsigned ah[2][4], al[2][4];
        #pragma unroll
        for (int kq = 0; kq < 2; kq++) {
            uint32_t a = sb + O_A1HI + (wid * 16 + arow) * 80 + kq * 32 + acol;
            ldmA(ah[kq], a);
            ldmA(al[kq], a + (O_A1LO - O_A1HI));
        }
        #pragma unroll
        for (int n8 = 0; n8 < 8; n8++) {
            unsigned bh[2][2], bl[2][2];
            #pragma unroll
            for (int kq = 0; kq < 2; kq++) {
                uint32_t a = sb + O_B1HI + (kc * 32 + kq * 16 + brow) * 144 + n8 * 16;
                ldmB(bh[kq], a);
                ldmB(bl[kq], a + (O_B1LO - O_B1HI));
            }
            #pragma unroll
            for (int kq = 0; kq < 2; kq++) {
                mmab(d[n8], ah[kq], bh[kq]);
                mmab(d[n8], ah[kq], bl[kq]);
                mmab(d[n8], al[kq], bh[kq]);
            }
        }
    }
    const float* sc = (const float*)(sm + O_P1SC);
    const float* tb = (const float*)(sm + O_P1TB);
    #pragma unroll
    for (int n8 = 0; n8 < 8; n8++) {
        int c = 8 * n8 + 2 * (lane & 3);
        float s0 = sc[c], s1 = sc[c + 1], t0 = tb[c], t1 = tb[c + 1];
        #pragma unroll
        for (int h = 0; h < 2; h++) {
            int site = base + wid * 16 + (lane >> 2) + 8 * h;
            if (site < NS) {
                float o0 = silu(d[n8][2 * h] * s0 + t0);
                float o1 = silu(d[n8][2 * h + 1] * s1 + t1);
                g_h[(size_t)site * 32 + (c >> 1)] = rn2(o0, o1);
            }
        }
    }
}

// ============================================================================
// k2: 512 threads, 128 sites/block.
// cv2: RN-A x RN-B (4 MMA/tile-warp), 64-row double-buffered items,
//      16 compute warps = (row-half) x (col-group).
// cv3: RN everything, warp = (row-half rh) x (16-col group ng); B loaded once.
// ============================================================================
#define O_ACC  0           // f32 [128][66] = 33792
#define O_G0   33792       // gather slot 0: 64*144 = 9216
#define O_G1   43008       // gather slot 1
#define O_W0   52224       // W2 slot 0: 9216 (RN)
#define O_W1   61440       // W2 slot 1
#define O_LP   70656       // u32 [9][128]
#define O_CN   75264       // int [12]
#define O_IT   75312       // int [20]
#define O_NI   75392
#define O_SC2  75408
#define O_TB2  75664
#define O_SC3  75920
#define O_TB3  76432
#define SM2    76944
#define O_A3   33792       // post-cv2: A3 tile 128*144=18432 over G0/G1 (33792..52224)
#define O_W3   0           // W3 RN image 64*272=17408 over ACC (0..17408)

__global__ __launch_bounds__(512, 2) void k2(
    const float* __restrict__ feat, const int* __restrict__ nbr,
    const float* __restrict__ g2, const float* __restrict__ b2,
    const float* __restrict__ m2, const float* __restrict__ v2,
    const float* __restrict__ g3, const float* __restrict__ b3,
    const float* __restrict__ m3, const float* __restrict__ v3,
    float* __restrict__ out)
{
    extern __shared__ char sm[];
    uint32_t sb = s2u(sm);
    int t = threadIdx.x, wid = t >> 5, lane = t & 31;
    int base = blockIdx.x * 128;
    unsigned* lp = (unsigned*)(sm + O_LP);
    int* cnt9 = (int*)(sm + O_CN);
    int* items = (int*)(sm + O_IT);
    float* acc = (float*)(sm + O_ACC);

    if (t < 64) {
        float s = g2[t] * rsqrtf(v2[t] + EPS);
        ((float*)(sm + O_SC2))[t] = s;
        ((float*)(sm + O_TB2))[t] = b2[t] - m2[t] * s;
    }
    if (t < 128) {
        float s = g3[t] * rsqrtf(v3[t] + EPS);
        ((float*)(sm + O_SC3))[t] = s;
        ((float*)(sm + O_TB3))[t] = b3[t] - m3[t] * s;
    }
    for (int q = t; q < 128 * 66; q += 512) acc[q] = 0.f;

    // compaction: warps 0..8, one offset each
    if (wid < 9) {
        int k = wid;
        int cbase = 0;
        #pragma unroll
        for (int g = 0; g < 4; g++) {
            int site = base + g * 32 + lane;
            int id = (site < NS) ? __ldg(&nbr[(size_t)k * NS + site]) : NS;
            bool val = id < NS;
            unsigned msk = __ballot_sync(0xffffffffu, val);
            if (val) {
                int p = cbase + __popc(msk & ((1u << lane) - 1u));
                lp[k * 128 + p] = ((unsigned)id << 8) | (g * 32 + lane);
            }
            cbase += __popc(msk);
        }
        if (lane == 0) cnt9[k] = cbase;
    }
    __syncthreads();
    if (t == 0) {
        int ni = 0;
        for (int k = 0; k < 9; k++)
            for (int c0 = 0; c0 < cnt9[k]; c0 += 64)
                items[ni++] = (k << 1) | (c0 >> 6);
        *(int*)(sm + O_NI) = ni;
    }
    __syncthreads();
    int nitems = *(int*)(sm + O_NI);

    auto issue_item = [&](int j) {
        int pk = items[j];
        int kk = pk >> 1, c0 = (pk & 1) << 6;
        int chunk = min(cnt9[kk] - c0, 64);
        uint32_t gb = sb + ((j & 1) ? O_G1 : O_G0);
        for (int q = t; q < chunk * 8; q += 512) {
            int r = q >> 3, s = q & 7;
            unsigned id = lp[kk * 128 + c0 + r] >> 8;
            cpa16(gb + r * 144 + s * 16, g_h + (size_t)id * 32 + s * 4);
        }
        uint32_t wbuf = sb + ((j & 1) ? O_W1 : O_W0);
        for (int q = t; q < 576; q += 512)
            cpa16(wbuf + q * 16, gW2r + kk * 4608 + q * 8);
    };

    int arow = ((lane >> 3) & 1) * 8 + (lane & 7);
    int acol = (lane >> 4) * 16;
    int brow = arow;
    int cg = wid & 7;     // cv2 col group (8 cols)
    int rg = wid >> 3;    // cv2 row-half: tiles rg, rg+2, ...

    issue_item(0);
    CP_COMMIT();

    for (int it = 0; it < nitems; it++) {
        __syncthreads();
        if (it + 1 < nitems) issue_item(it + 1);
        CP_COMMIT();
        if (it + 1 < nitems) CP_WAIT1(); else CP_WAIT0();
        __syncthreads();

        int pk = items[it];
        int kk = pk >> 1, c0 = (pk & 1) << 6;
        int chunk = min(cnt9[kk] - c0, 64);
        uint32_t gb = sb + ((it & 1) ? O_G1 : O_G0);
        uint32_t wbuf = sb + ((it & 1) ? O_W1 : O_W0);
        int mtiles = (chunk + 15) >> 4;

        unsigned bf[4][2];
        #pragma unroll
        for (int kq = 0; kq < 4; kq++)
            ldmB(bf[kq], wbuf + (kq * 16 + brow) * 144 + cg * 16);
        for (int mt = rg; mt < mtiles; mt += 2) {
            float dd[4] = {};
            unsigned ah[4];
            #pragma unroll
            for (int kq = 0; kq < 4; kq++) {
                ldmA(ah, gb + (mt * 16 + arow) * 144 + kq * 32 + acol);
                mmab(dd, ah, bf[kq]);
            }
            int c = 8 * cg + 2 * (lane & 3);
            #pragma unroll
            for (int h = 0; h < 2; h++) {
                int gr = mt * 16 + (lane >> 2) + 8 * h;
                if (gr < chunk) {
                    int rw = lp[kk * 128 + c0 + gr] & 255;
                    float2* ap = (float2*)(acc + rw * 66 + c);
                    float2 v = *ap;
                    v.x += dd[2 * h]; v.y += dd[2 * h + 1];
                    *ap = v;
                }
            }
        }
    }
    __syncthreads();
    // BN2 + SiLU -> RN bf16 A3 tile (over gather slots)
    const float* sc2 = (const float*)(sm + O_SC2);
    const float* tb2 = (const float*)(sm + O_TB2);
    #pragma unroll
    for (int i = 0; i < 8; i++) {
        int idx = t + 512 * i, r = idx >> 5, p = idx & 31;
        float x0 = acc[r * 66 + 2 * p] * sc2[2 * p] + tb2[2 * p];
        float x1 = acc[r * 66 + 2 * p + 1] * sc2[2 * p + 1] + tb2[2 * p + 1];
        *(unsigned*)(sm + O_A3 + r * 144 + p * 4) = rn2(silu(x0), silu(x1));
    }
    __syncthreads();   // ACC reads done before W3 overwrites it
    for (int q = t; q < 1088; q += 512)
        cpa16(sb + O_W3 + q * 16, gW3r + q * 8);
    CP_COMMIT();
    CP_WAIT0();
    __syncthreads();
    // cv3: warp = (row-half rh: 64 rows) x (16-col group ng); B held in regs
    const float* sc3 = (const float*)(sm + O_SC3);
    const float* tb3 = (const float*)(sm + O_TB3);
    int rh = wid >> 3, ng = wid & 7;
    unsigned bf3[2][4][2];
    #pragma unroll
    for (int j = 0; j < 2; j++)
        #pragma unroll
        for (int kq = 0; kq < 4; kq++)
            ldmB(bf3[j][kq], sb + O_W3 + (kq * 16 + brow) * 272 + (ng * 2 + j) * 16);
    #pragma unroll
    for (int tile = 0; tile < 4; tile++) {
        int r0 = rh * 64 + tile * 16;
        unsigned ah[4][4];
        #pragma unroll
        for (int kq = 0; kq < 4; kq++)
            ldmA(ah[kq], sb + O_A3 + (r0 + arow) * 144 + kq * 32 + acol);
        #pragma unroll
        for (int j = 0; j < 2; j++) {
            float dd[4] = {};
            #pragma unroll
            for (int kq = 0; kq < 4; kq++)
                mmab(dd, ah[kq], bf3[j][kq]);
            int c = ng * 16 + j * 8 + 2 * (lane & 3);
            float s0 = sc3[c], s1 = sc3[c + 1], t0 = tb3[c], t1 = tb3[c + 1];
            #pragma unroll
            for (int h = 0; h < 2; h++) {
                int site = base + r0 + (lane >> 2) + 8 * h;
                if (site < NS) {
                    float2 f = *(const float2*)(feat + (size_t)site * 128 + c);
                    float o0 = silu(dd[2 * h] * s0 + t0 + f.x);
                    float o1 = silu(dd[2 * h + 1] * s1 + t1 + f.y);
                    *(float2*)(out + (size_t)site * 128 + c) = make_float2(o0, o1);
                }
            }
        }
    }
}

// ============================================================================
extern "C" void kernel_launch(void* const* d_in, const int* in_sizes, int n_in,
                              void* d_out, int out_size) {
    const float* feat = (const float*)d_in[0];
    const int*   nbr  = (const int*)d_in[1];
    const float* W1 = (const float*)d_in[2];
    const float* W2 = (const float*)d_in[3];
    const float* W3 = (const float*)d_in[4];
    const float* g1 = (const float*)d_in[5];
    const float* b1 = (const float*)d_in[6];
    const float* m1 = (const float*)d_in[7];
    const float* v1 = (const float*)d_in[8];
    const float* g2 = (const float*)d_in[9];
    const float* b2 = (const float*)d_in[10];
    const float* m2 = (const float*)d_in[11];
    const float* v2 = (const float*)d_in[12];
    const float* g3 = (const float*)d_in[13];
    const float* b3 = (const float*)d_in[14];
    const float* m3 = (const float*)d_in[15];
    const float* v3 = (const float*)d_in[16];
    float* out = (float*)d_out;

    cudaFuncSetAttribute(k1, cudaFuncAttributeMaxDynamicSharedMemorySize, SM1);
    cudaFuncSetAttribute(k2, cudaFuncAttributeMaxDynamicSharedMemorySize, SM2);

    int grid = (NS + 127) / 128;   // 3907
    kdum<<<1, 32>>>();
    k0<<<232, 256>>>(W1, W2, W3);
    k1<<<grid, 256, SM1>>>(feat, g1, b1, m1, v1);
    k2<<<grid, 512, SM2>>>(feat, nbr, g2, b2, m2, v2, g3, b3, m3, v3, out);
}